// round 7
// baseline (speedup 1.0000x reference)
#include <cuda_runtime.h>
#include <cuda_bf16.h>
#include <math.h>
#include <stdint.h>

#define E_DIM 256
#define N_MAX 8192
#define TILE 128
#define CHUNK 64
#define NCHUNK (E_DIM / CHUNK)      // 4
#define SAW 72                       // smem row stride in bf16 (144B): 4-bank skew, ldmatrix conflict-free
#define STAGE_BYTES (TILE * SAW * 2) // 18432

// ---------------- device scratch ----------------
__device__ __nv_bfloat16 g_xb[N_MAX * E_DIM];
__device__ int      g_target[N_MAX];
__device__ float    g_invcnt[4];
__device__ float    g_wbase;
__device__ int      g_last;
__device__ double   g_sum;
__device__ unsigned g_done;

// ---------------- helpers ----------------
__device__ __forceinline__ uint32_t smem_u32(const void* p) {
    uint32_t a;
    asm("{ .reg .u64 t; cvta.to.shared.u64 t, %1; cvt.u32.u64 %0, t; }" : "=r"(a) : "l"(p));
    return a;
}
__device__ __forceinline__ void cp_async16(uint32_t dst, const void* src) {
    asm volatile("cp.async.cg.shared.global [%0], [%1], 16;" :: "r"(dst), "l"(src) : "memory");
}
__device__ __forceinline__ void cp_commit() {
    asm volatile("cp.async.commit_group;" ::: "memory");
}
__device__ __forceinline__ void cp_wait1() {
    asm volatile("cp.async.wait_group 1;" ::: "memory");
}
__device__ __forceinline__ void cp_wait0() {
    asm volatile("cp.async.wait_group 0;" ::: "memory");
}
__device__ __forceinline__ void ldsm_x4(uint32_t* r, uint32_t addr) {
    asm volatile("ldmatrix.sync.aligned.m8n8.x4.shared.b16 {%0,%1,%2,%3}, [%4];"
                 : "=r"(r[0]), "=r"(r[1]), "=r"(r[2]), "=r"(r[3]) : "r"(addr));
}
__device__ __forceinline__ void mma_16816(float* d, const uint32_t* a, const uint32_t* b) {
    asm volatile(
        "mma.sync.aligned.m16n8k16.row.col.f32.bf16.bf16.f32 "
        "{%0,%1,%2,%3}, {%4,%5,%6,%7}, {%8,%9}, {%0,%1,%2,%3};"
        : "+f"(d[0]), "+f"(d[1]), "+f"(d[2]), "+f"(d[3])
        : "r"(a[0]), "r"(a[1]), "r"(a[2]), "r"(a[3]), "r"(b[0]), "r"(b[1]));
}

// ---------------- prep: normalize rows + (block 0) target setup ----------------
__global__ void prep_kernel(const float* __restrict__ x, const int* __restrict__ traw, int n) {
    const int row = blockIdx.x;
    const int t = threadIdx.x;

    float v = x[row * E_DIM + t];
    float s = v * v;
    #pragma unroll
    for (int o = 16; o > 0; o >>= 1) s += __shfl_xor_sync(0xffffffffu, s, o);
    __shared__ float ws[8];
    __shared__ float s_inv;
    if ((t & 31) == 0) ws[t >> 5] = s;
    __syncthreads();
    if (t == 0) {
        float z = 0.f;
        #pragma unroll
        for (int i = 0; i < 8; i++) z += ws[i];
        s_inv = 1.0f / fmaxf(sqrtf(z), 1e-8f);
    }
    __syncthreads();
    g_xb[row * E_DIM + t] = __float2bfloat16(v * s_inv);

    if (row == 0) {
        __shared__ int s_cnt[4];
        __shared__ int s_flag;
        if (t < 4) s_cnt[t] = 0;
        if (t == 0) { s_flag = 0; g_sum = 0.0; g_done = 0u; }
        __syncthreads();
        int f = 0;
        for (int i = 2 * t + 1; i < n; i += 2 * blockDim.x)
            if (traw[i] != 0) f = 1;
        if (f) atomicOr(&s_flag, 1);
        __syncthreads();
        const int is64 = (s_flag == 0);
        for (int i = t; i < n; i += blockDim.x) {
            int tv = is64 ? traw[2 * i] : traw[i];
            g_target[i] = tv;
            atomicAdd(&s_cnt[tv & 3], 1);
        }
        __syncthreads();
        if (t == 0) {
            float wb = 0.f;
            int L = 0;
            for (int c = 0; c < 4; c++) {
                float ic = (s_cnt[c] > 0) ? (1.0f / (float)s_cnt[c]) : 0.0f;
                g_invcnt[c] = ic;
                if (s_cnt[c] > 0) { wb += ic; L = c; }
            }
            g_wbase = wb;
            g_last = L;
        }
    }
}

// ---------------- pair kernel: 128 threads, 4 warps x (64x64) ----------------
#define OFF_TA   0
#define OFF_TB   512
#define OFF_RED  1024
#define OFF_A    1536
#define OFF_B    (OFF_A + 2 * STAGE_BYTES)
#define SMEM_TOTAL (OFF_B + 2 * STAGE_BYTES)

__global__ __launch_bounds__(128, 2) void pair_kernel(float* __restrict__ out,
                                                      int nTiles, int nBlocks, float invN) {
    extern __shared__ char smem[];
    const uint32_t sbase = smem_u32(smem);
    const int tid = threadIdx.x;
    const int wid = tid >> 5;
    const int lid = tid & 31;

    // block -> (bi, bj), bj >= bi
    int idx = blockIdx.x;
    int bi = 0;
    while (idx >= nTiles - bi) { idx -= nTiles - bi; bi++; }
    const int bj = bi + idx;
    const int row0 = bi * TILE;
    const int col0 = bj * TILE;

    const uint4* __restrict__ srcA = (const uint4*)(g_xb + (size_t)row0 * E_DIM);
    const uint4* __restrict__ srcB = (const uint4*)(g_xb + (size_t)col0 * E_DIM);

    // chunk loader: per tile 128 rows x 8 uint4 (64 cols); both tiles
    auto load_chunk = [&](int c, int stage) {
        const uint32_t dA = sbase + OFF_A + stage * STAGE_BYTES;
        const uint32_t dB = sbase + OFF_B + stage * STAGE_BYTES;
        #pragma unroll
        for (int it = 0; it < 8; it++) {
            int v = tid + it * 128;          // 0..1023
            int row = v >> 3;
            int q = v & 7;
            uint32_t d = (uint32_t)(row * SAW + q * 8) * 2u;
            int gsrc = row * 32 + c * 8 + q;
            cp_async16(dA + d, srcA + gsrc);
            cp_async16(dB + d, srcB + gsrc);
        }
        cp_commit();
    };

    int* tA = (int*)(smem + OFF_TA);
    int* tB = (int*)(smem + OFF_TB);
    if (tid < TILE) { tA[tid] = g_target[row0 + tid]; tB[tid] = g_target[col0 + tid]; }

    load_chunk(0, 0);

    // warp decomposition: wm in {0,1} -> 64 rows, wn in {0,1} -> 64 cols
    const int wm = wid & 1;
    const int wn = wid >> 1;
    const int rbase = wm * 64;
    const int cbase = wn * 64;

    float acc[4][8][4];
    #pragma unroll
    for (int mt = 0; mt < 4; mt++)
        #pragma unroll
        for (int nt = 0; nt < 8; nt++)
            #pragma unroll
            for (int q = 0; q < 4; q++) acc[mt][nt][q] = 0.f;

    const int mi = lid >> 3;
    const int mr = lid & 7;
    // A x4: m0 rows+0 k+0 | m1 rows+8 k+0 | m2 rows+0 k+8 | m3 rows+8 k+8
    const uint32_t aOff = (uint32_t)((rbase + mr + (mi & 1) * 8) * SAW + (mi >> 1) * 8) * 2u;
    // B x4: m0 n+0 k+0 | m1 n+0 k+8 | m2 n+8 k+0 | m3 n+8 k+8
    const uint32_t bOff = (uint32_t)((cbase + mr + (mi >> 1) * 8) * SAW + (mi & 1) * 8) * 2u;

    #pragma unroll
    for (int c = 0; c < NCHUNK; c++) {
        const int stage = c & 1;
        if (c + 1 < NCHUNK) {
            load_chunk(c + 1, (c + 1) & 1);
            cp_wait1();
        } else {
            cp_wait0();
        }
        __syncthreads();

        const uint32_t aBase = sbase + OFF_A + stage * STAGE_BYTES + aOff;
        const uint32_t bBase = sbase + OFF_B + stage * STAGE_BYTES + bOff;

        #pragma unroll
        for (int k = 0; k < CHUNK; k += 16) {
            uint32_t af[4][4];
            uint32_t bf[8][2];
            #pragma unroll
            for (int mt = 0; mt < 4; mt++)
                ldsm_x4(af[mt], aBase + (uint32_t)(mt * 16 * SAW + k) * 2u);
            #pragma unroll
            for (int bt = 0; bt < 4; bt++) {
                uint32_t r[4];
                ldsm_x4(r, bBase + (uint32_t)(bt * 16 * SAW + k) * 2u);
                bf[2 * bt][0] = r[0]; bf[2 * bt][1] = r[1];
                bf[2 * bt + 1][0] = r[2]; bf[2 * bt + 1][1] = r[3];
            }
            #pragma unroll
            for (int mt = 0; mt < 4; mt++)
                #pragma unroll
                for (int nt = 0; nt < 8; nt++)
                    mma_16816(acc[mt][nt], af[mt], bf[nt]);
        }
        __syncthreads();   // protect stage buffer before it is reloaded
    }

    // fused epilogue
    const float wbase = g_wbase;
    const int L = g_last;
    const float ic0 = g_invcnt[0], ic1 = g_invcnt[1], ic2 = g_invcnt[2], ic3 = g_invcnt[3];
    const int g = lid >> 2;
    const int t4 = lid & 3;

    float local = 0.f;
    #pragma unroll
    for (int mt = 0; mt < 4; mt++) {
        #pragma unroll
        for (int rh = 0; rh < 2; rh++) {
            const int ri = rbase + mt * 16 + g + rh * 8;
            const int gi = row0 + ri;
            const int ta = tA[ri];
            const float ica = (ta == 0) ? ic0 : (ta == 1) ? ic1 : (ta == 2) ? ic2 : ic3;
            const bool aL = (ta == L);
            #pragma unroll
            for (int nt = 0; nt < 8; nt++) {
                #pragma unroll
                for (int cc = 0; cc < 2; cc++) {
                    const int cj = cbase + nt * 8 + 2 * t4 + cc;
                    const int gj = col0 + cj;
                    if (gj > gi) {
                        const float cs = acc[mt][nt][rh * 2 + cc];
                        const int tb = tB[cj];
                        const float icb = (tb == 0) ? ic0 : (tb == 1) ? ic1 : (tb == 2) ? ic2 : ic3;
                        const float w = (ta == tb) ? wbase : (wbase - ica - icb);
                        local += w * (1.0f - cs);
                        if (aL != (tb == L)) local += fmaxf(cs - 0.5f, 0.0f);
                    }
                }
            }
        }
    }

    // block reduce (4 warps)
    #pragma unroll
    for (int o = 16; o > 0; o >>= 1) local += __shfl_xor_sync(0xffffffffu, local, o);
    float* red = (float*)(smem + OFF_RED);
    if (lid == 0) red[wid] = local;
    __syncthreads();
    if (tid == 0) {
        float z = red[0] + red[1] + red[2] + red[3];
        atomicAdd(&g_sum, (double)z);
        __threadfence();
        unsigned done = atomicAdd(&g_done, 1u);
        if (done == (unsigned)(nBlocks - 1)) {
            double total = *(volatile double*)&g_sum;
            out[0] = (float)(total * (double)invN);
        }
    }
}

extern "C" void kernel_launch(void* const* d_in, const int* in_sizes, int n_in,
                              void* d_out, int out_size) {
    const float* x = (const float*)d_in[0];
    const int* traw = (const int*)d_in[1];
    float* out = (float*)d_out;

    const int n = in_sizes[1];
    const int nTiles = n / TILE;
    const int nBlocks = nTiles * (nTiles + 1) / 2;

    cudaFuncSetAttribute(pair_kernel, cudaFuncAttributeMaxDynamicSharedMemorySize, SMEM_TOTAL);

    prep_kernel<<<n, 256>>>(x, traw, n);
    pair_kernel<<<nBlocks, 128, SMEM_TOTAL>>>(out, nTiles, nBlocks, 1.0f / (float)n);
}

// round 8
// speedup vs baseline: 1.3495x; 1.3495x over previous
#include <cuda_runtime.h>
#include <cuda_bf16.h>
#include <math.h>
#include <stdint.h>

#define E_DIM 256
#define N_MAX 8192
#define TILE 128
#define CHUNK 64
#define NCHUNK (E_DIM / CHUNK)      // 4
#define NSTAGE 3
#define SAW 72                       // smem row stride in bf16 (144B): 4-bank skew, ldmatrix conflict-free
#define STAGE_BYTES (TILE * SAW * 2) // 18432

// ---------------- device scratch ----------------
__device__ __nv_bfloat16 g_xb[N_MAX * E_DIM];
__device__ int      g_target[N_MAX];
__device__ float    g_invcnt[4];
__device__ float    g_wbase;
__device__ int      g_last;
__device__ double   g_sum;
__device__ unsigned g_done;

// ---------------- helpers ----------------
__device__ __forceinline__ uint32_t smem_u32(const void* p) {
    uint32_t a;
    asm("{ .reg .u64 t; cvta.to.shared.u64 t, %1; cvt.u32.u64 %0, t; }" : "=r"(a) : "l"(p));
    return a;
}
__device__ __forceinline__ void cp_async16(uint32_t dst, const void* src) {
    asm volatile("cp.async.cg.shared.global [%0], [%1], 16;" :: "r"(dst), "l"(src) : "memory");
}
__device__ __forceinline__ void cp_commit() {
    asm volatile("cp.async.commit_group;" ::: "memory");
}
__device__ __forceinline__ void cp_wait1() {
    asm volatile("cp.async.wait_group 1;" ::: "memory");
}
__device__ __forceinline__ void ldsm_x4(uint32_t* r, uint32_t addr) {
    asm volatile("ldmatrix.sync.aligned.m8n8.x4.shared.b16 {%0,%1,%2,%3}, [%4];"
                 : "=r"(r[0]), "=r"(r[1]), "=r"(r[2]), "=r"(r[3]) : "r"(addr));
}
__device__ __forceinline__ void mma_16816(float* d, const uint32_t* a, const uint32_t* b) {
    asm volatile(
        "mma.sync.aligned.m16n8k16.row.col.f32.bf16.bf16.f32 "
        "{%0,%1,%2,%3}, {%4,%5,%6,%7}, {%8,%9}, {%0,%1,%2,%3};"
        : "+f"(d[0]), "+f"(d[1]), "+f"(d[2]), "+f"(d[3])
        : "r"(a[0]), "r"(a[1]), "r"(a[2]), "r"(a[3]), "r"(b[0]), "r"(b[1]));
}

// ---------------- prep: normalize rows + (block 0) target setup ----------------
__global__ void prep_kernel(const float* __restrict__ x, const int* __restrict__ traw, int n) {
    const int row = blockIdx.x;
    const int t = threadIdx.x;

    float v = x[row * E_DIM + t];
    float s = v * v;
    #pragma unroll
    for (int o = 16; o > 0; o >>= 1) s += __shfl_xor_sync(0xffffffffu, s, o);
    __shared__ float ws[8];
    __shared__ float s_inv;
    if ((t & 31) == 0) ws[t >> 5] = s;
    __syncthreads();
    if (t == 0) {
        float z = 0.f;
        #pragma unroll
        for (int i = 0; i < 8; i++) z += ws[i];
        s_inv = 1.0f / fmaxf(sqrtf(z), 1e-8f);
    }
    __syncthreads();
    g_xb[row * E_DIM + t] = __float2bfloat16(v * s_inv);

    if (row == 0) {
        __shared__ int s_cnt[4];
        __shared__ int s_flag;
        if (t < 4) s_cnt[t] = 0;
        if (t == 0) { s_flag = 0; g_sum = 0.0; g_done = 0u; }
        __syncthreads();
        int f = 0;
        for (int i = 2 * t + 1; i < n; i += 2 * blockDim.x)
            if (traw[i] != 0) f = 1;
        if (f) atomicOr(&s_flag, 1);
        __syncthreads();
        const int is64 = (s_flag == 0);
        for (int i = t; i < n; i += blockDim.x) {
            int tv = is64 ? traw[2 * i] : traw[i];
            g_target[i] = tv;
            atomicAdd(&s_cnt[tv & 3], 1);
        }
        __syncthreads();
        if (t == 0) {
            float wb = 0.f;
            int L = 0;
            for (int c = 0; c < 4; c++) {
                float ic = (s_cnt[c] > 0) ? (1.0f / (float)s_cnt[c]) : 0.0f;
                g_invcnt[c] = ic;
                if (s_cnt[c] > 0) { wb += ic; L = c; }
            }
            g_wbase = wb;
            g_last = L;
        }
    }
}

// ---------------- pair kernel: 256 threads, 8 warps x (64x32), 3-stage pipeline ----------------
#define OFF_TA   0
#define OFF_TB   512
#define OFF_RED  1024
#define OFF_A    1536
#define OFF_B    (OFF_A + NSTAGE * STAGE_BYTES)
#define SMEM_TOTAL (OFF_B + NSTAGE * STAGE_BYTES)

__global__ __launch_bounds__(256, 2) void pair_kernel(float* __restrict__ out,
                                                      int nTiles, int nBlocks, float invN) {
    extern __shared__ char smem[];
    const uint32_t sbase = smem_u32(smem);
    const int tid = threadIdx.x;
    const int wid = tid >> 5;
    const int lid = tid & 31;

    // block -> (bi, bj), bj >= bi
    int idx = blockIdx.x;
    int bi = 0;
    while (idx >= nTiles - bi) { idx -= nTiles - bi; bi++; }
    const int bj = bi + idx;
    const int row0 = bi * TILE;
    const int col0 = bj * TILE;

    const uint4* __restrict__ srcA = (const uint4*)(g_xb + (size_t)row0 * E_DIM);
    const uint4* __restrict__ srcB = (const uint4*)(g_xb + (size_t)col0 * E_DIM);

    // chunk loader: per tile 128 rows x 8 uint4 (64 cols); both tiles.
    // Always commits a group (possibly empty) to keep wait_group counting aligned.
    auto load_chunk = [&](int c) {
        if (c < NCHUNK) {
            const int stage = c % NSTAGE;
            const uint32_t dA = sbase + OFF_A + stage * STAGE_BYTES;
            const uint32_t dB = sbase + OFF_B + stage * STAGE_BYTES;
            #pragma unroll
            for (int it = 0; it < 4; it++) {
                int v = tid + it * 256;          // 0..1023
                int row = v >> 3;
                int q = v & 7;
                uint32_t d = (uint32_t)(row * SAW + q * 8) * 2u;
                int gsrc = row * 32 + c * 8 + q;
                cp_async16(dA + d, srcA + gsrc);
                cp_async16(dB + d, srcB + gsrc);
            }
        }
        cp_commit();
    };

    int* tA = (int*)(smem + OFF_TA);
    int* tB = (int*)(smem + OFF_TB);
    if (tid < TILE) { tA[tid] = g_target[row0 + tid]; tB[tid] = g_target[col0 + tid]; }

    // prologue: chunks 0 and 1 in flight
    load_chunk(0);
    load_chunk(1);

    // warp decomposition: wm in {0,1} -> 64 rows, wn in {0..3} -> 32 cols
    const int wm = wid & 1;
    const int wn = wid >> 1;
    const int rbase = wm * 64;
    const int cbase = wn * 32;

    float acc[4][4][4];
    #pragma unroll
    for (int mt = 0; mt < 4; mt++)
        #pragma unroll
        for (int nt = 0; nt < 4; nt++)
            #pragma unroll
            for (int q = 0; q < 4; q++) acc[mt][nt][q] = 0.f;

    const int mi = lid >> 3;
    const int mr = lid & 7;
    // A x4: m0 rows+0 k+0 | m1 rows+8 k+0 | m2 rows+0 k+8 | m3 rows+8 k+8
    const uint32_t aOff = (uint32_t)((rbase + mr + (mi & 1) * 8) * SAW + (mi >> 1) * 8) * 2u;
    // B x4: m0 n+0 k+0 | m1 n+0 k+8 | m2 n+8 k+0 | m3 n+8 k+8
    const uint32_t bOff = (uint32_t)((cbase + mr + (mi >> 1) * 8) * SAW + (mi & 1) * 8) * 2u;

    #pragma unroll
    for (int c = 0; c < NCHUNK; c++) {
        const int stage = c % NSTAGE;

        cp_wait1();        // chunk c complete (<=1 younger group pending)
        __syncthreads();   // (a) data visible to all warps  (b) all warps done reading stage (c-1)%NSTAGE

        // issue load for chunk c+2 into stage (c+2)%NSTAGE == (c-1)%NSTAGE — safe after the sync
        load_chunk(c + 2);

        const uint32_t aBase = sbase + OFF_A + stage * STAGE_BYTES + aOff;
        const uint32_t bBase = sbase + OFF_B + stage * STAGE_BYTES + bOff;

        #pragma unroll
        for (int k = 0; k < CHUNK; k += 16) {
            uint32_t af[4][4];
            uint32_t bf[4][2];
            #pragma unroll
            for (int mt = 0; mt < 4; mt++)
                ldsm_x4(af[mt], aBase + (uint32_t)(mt * 16 * SAW + k) * 2u);
            #pragma unroll
            for (int bt = 0; bt < 2; bt++) {
                uint32_t r[4];
                ldsm_x4(r, bBase + (uint32_t)(bt * 16 * SAW + k) * 2u);
                bf[2 * bt][0] = r[0]; bf[2 * bt][1] = r[1];
                bf[2 * bt + 1][0] = r[2]; bf[2 * bt + 1][1] = r[3];
            }
            #pragma unroll
            for (int mt = 0; mt < 4; mt++)
                #pragma unroll
                for (int nt = 0; nt < 4; nt++)
                    mma_16816(acc[mt][nt], af[mt], bf[nt]);
        }
    }

    // fused epilogue
    const float wbase = g_wbase;
    const int L = g_last;
    const float ic0 = g_invcnt[0], ic1 = g_invcnt[1], ic2 = g_invcnt[2], ic3 = g_invcnt[3];
    const int g = lid >> 2;
    const int t4 = lid & 3;

    float local = 0.f;
    #pragma unroll
    for (int mt = 0; mt < 4; mt++) {
        #pragma unroll
        for (int rh = 0; rh < 2; rh++) {
            const int ri = rbase + mt * 16 + g + rh * 8;
            const int gi = row0 + ri;
            const int ta = tA[ri];
            const float ica = (ta == 0) ? ic0 : (ta == 1) ? ic1 : (ta == 2) ? ic2 : ic3;
            const bool aL = (ta == L);
            #pragma unroll
            for (int nt = 0; nt < 4; nt++) {
                #pragma unroll
                for (int cc = 0; cc < 2; cc++) {
                    const int cj = cbase + nt * 8 + 2 * t4 + cc;
                    const int gj = col0 + cj;
                    if (gj > gi) {
                        const float cs = acc[mt][nt][rh * 2 + cc];
                        const int tb = tB[cj];
                        const float icb = (tb == 0) ? ic0 : (tb == 1) ? ic1 : (tb == 2) ? ic2 : ic3;
                        const float w = (ta == tb) ? wbase : (wbase - ica - icb);
                        local += w * (1.0f - cs);
                        if (aL != (tb == L)) local += fmaxf(cs - 0.5f, 0.0f);
                    }
                }
            }
        }
    }

    // block reduce
    #pragma unroll
    for (int o = 16; o > 0; o >>= 1) local += __shfl_xor_sync(0xffffffffu, local, o);
    float* red = (float*)(smem + OFF_RED);
    if (lid == 0) red[wid] = local;
    __syncthreads();
    if (tid == 0) {
        float z = 0.f;
        #pragma unroll
        for (int i = 0; i < 8; i++) z += red[i];
        atomicAdd(&g_sum, (double)z);
        __threadfence();
        unsigned done = atomicAdd(&g_done, 1u);
        if (done == (unsigned)(nBlocks - 1)) {
            double total = *(volatile double*)&g_sum;
            out[0] = (float)(total * (double)invN);
        }
    }
}

extern "C" void kernel_launch(void* const* d_in, const int* in_sizes, int n_in,
                              void* d_out, int out_size) {
    const float* x = (const float*)d_in[0];
    const int* traw = (const int*)d_in[1];
    float* out = (float*)d_out;

    const int n = in_sizes[1];
    const int nTiles = n / TILE;
    const int nBlocks = nTiles * (nTiles + 1) / 2;

    cudaFuncSetAttribute(pair_kernel, cudaFuncAttributeMaxDynamicSharedMemorySize, SMEM_TOTAL);

    prep_kernel<<<n, 256>>>(x, traw, n);
    pair_kernel<<<nBlocks, 256, SMEM_TOTAL>>>(out, nTiles, nBlocks, 1.0f / (float)n);
}

// round 9
// speedup vs baseline: 1.6998x; 1.2596x over previous
#include <cuda_runtime.h>
#include <cuda_bf16.h>
#include <math.h>
#include <stdint.h>

#define E_DIM 256
#define N_MAX 8192
#define TILE 128
#define CHUNK 64
#define NCHUNK (E_DIM / CHUNK)      // 4
#define NSTAGE 3
#define SAW 72                       // smem row stride in bf16 (144B)
#define STAGE_BYTES (TILE * SAW * 2) // 18432

// ---------------- device scratch ----------------
__device__ __nv_bfloat16 g_xb[N_MAX * E_DIM];   // normalized rows bf16
__device__ __nv_bfloat16 g_P[N_MAX * E_DIM];    // gathered class-L rows (padded w/ zeros)
__device__ __nv_bfloat16 g_Q[N_MAX * E_DIM];    // gathered non-L rows (padded w/ zeros)
__device__ int      g_target[N_MAX];
__device__ int      g_rowsL[N_MAX];
__device__ int      g_rowsN[N_MAX];
__device__ float    g_S[4][E_DIM];              // per-class sums of xn
__device__ int      g_cntL, g_cntN, g_padL, g_padN;
__device__ double   g_base;                     // closed-form same-class loss (times 1, pre /n)
__device__ double   g_sum;                      // relu margin sum

// ---------------- helpers ----------------
__device__ __forceinline__ uint32_t smem_u32(const void* p) {
    uint32_t a;
    asm("{ .reg .u64 t; cvta.to.shared.u64 t, %1; cvt.u32.u64 %0, t; }" : "=r"(a) : "l"(p));
    return a;
}
__device__ __forceinline__ void cp_async16(uint32_t dst, const void* src) {
    asm volatile("cp.async.cg.shared.global [%0], [%1], 16;" :: "r"(dst), "l"(src) : "memory");
}
__device__ __forceinline__ void cp_commit() {
    asm volatile("cp.async.commit_group;" ::: "memory");
}
__device__ __forceinline__ void cp_wait1() {
    asm volatile("cp.async.wait_group 1;" ::: "memory");
}
__device__ __forceinline__ void ldsm_x4(uint32_t* r, uint32_t addr) {
    asm volatile("ldmatrix.sync.aligned.m8n8.x4.shared.b16 {%0,%1,%2,%3}, [%4];"
                 : "=r"(r[0]), "=r"(r[1]), "=r"(r[2]), "=r"(r[3]) : "r"(addr));
}
__device__ __forceinline__ void mma_16816(float* d, const uint32_t* a, const uint32_t* b) {
    asm volatile(
        "mma.sync.aligned.m16n8k16.row.col.f32.bf16.bf16.f32 "
        "{%0,%1,%2,%3}, {%4,%5,%6,%7}, {%8,%9}, {%0,%1,%2,%3};"
        : "+f"(d[0]), "+f"(d[1]), "+f"(d[2]), "+f"(d[3])
        : "r"(a[0]), "r"(a[1]), "r"(a[2]), "r"(a[3]), "r"(b[0]), "r"(b[1]));
}

// ---------------- K1: normalize rows + (block 0) target decode & zeroing ----------------
__global__ void prep_kernel(const float* __restrict__ x, const int* __restrict__ traw, int n) {
    const int row = blockIdx.x;
    const int t = threadIdx.x;

    float v = x[row * E_DIM + t];
    float s = v * v;
    #pragma unroll
    for (int o = 16; o > 0; o >>= 1) s += __shfl_xor_sync(0xffffffffu, s, o);
    __shared__ float ws[8];
    __shared__ float s_inv;
    if ((t & 31) == 0) ws[t >> 5] = s;
    __syncthreads();
    if (t == 0) {
        float z = 0.f;
        #pragma unroll
        for (int i = 0; i < 8; i++) z += ws[i];
        s_inv = 1.0f / fmaxf(sqrtf(z), 1e-8f);
    }
    __syncthreads();
    g_xb[row * E_DIM + t] = __float2bfloat16(v * s_inv);

    if (row == 0) {
        __shared__ int s_flag;
        if (t == 0) { s_flag = 0; g_sum = 0.0; }
        // zero class sums
        for (int i = t; i < 4 * E_DIM; i += blockDim.x) ((float*)g_S)[i] = 0.f;
        __syncthreads();
        int f = 0;
        for (int i = 2 * t + 1; i < n; i += 2 * blockDim.x)
            if (traw[i] != 0) f = 1;
        if (f) atomicOr(&s_flag, 1);
        __syncthreads();
        const int is64 = (s_flag == 0);
        for (int i = t; i < n; i += blockDim.x)
            g_target[i] = is64 ? traw[2 * i] : traw[i];
    }
}

// ---------------- K2: per-class sums of normalized rows ----------------
__global__ void classsum_kernel(int n) {
    const int t = threadIdx.x;          // dim
    const int r0 = blockIdx.x * 32;     // 32 rows per block
    float a0 = 0.f, a1 = 0.f, a2 = 0.f, a3 = 0.f;
    #pragma unroll 4
    for (int r = 0; r < 32; r++) {
        const int row = r0 + r;
        const float v = __bfloat162float(g_xb[row * E_DIM + t]);
        const int c = g_target[row];
        if (c == 0) a0 += v; else if (c == 1) a1 += v; else if (c == 2) a2 += v; else a3 += v;
    }
    atomicAdd(&g_S[0][t], a0);
    atomicAdd(&g_S[1][t], a1);
    atomicAdd(&g_S[2][t], a2);
    atomicAdd(&g_S[3][t], a3);
}

// ---------------- K3: closed-form same-class loss + gather lists ----------------
__global__ void scalar_kernel(int n) {
    const int t = threadIdx.x;
    __shared__ int cnt[4];
    __shared__ int sL, sN, Lsh;
    __shared__ float sacc[8];   // [0..3]=|S_i|^2, [4..7]=|S_all-S_i|^2
    if (t < 4) cnt[t] = 0;
    if (t < 8) sacc[t] = 0.f;
    if (t == 0) { sL = 0; sN = 0; }
    __syncthreads();

    for (int i = t; i < n; i += blockDim.x) atomicAdd(&cnt[g_target[i] & 3], 1);
    __syncthreads();
    if (t == 0) Lsh = (cnt[3] > 0) ? 3 : (cnt[2] > 0) ? 2 : (cnt[1] > 0) ? 1 : 0;
    __syncthreads();
    const int L = Lsh;

    for (int i = t; i < n; i += blockDim.x) {
        if (g_target[i] == L) g_rowsL[atomicAdd(&sL, 1)] = i;
        else                  g_rowsN[atomicAdd(&sN, 1)] = i;
    }

    // per-dim contributions (t = dim, 256 dims, 256 threads)
    const float s0 = g_S[0][t], s1 = g_S[1][t], s2 = g_S[2][t], s3 = g_S[3][t];
    const float sAll = s0 + s1 + s2 + s3;
    const float si[4] = {s0, s1, s2, s3};
    #pragma unroll
    for (int i = 0; i < 4; i++) {
        atomicAdd(&sacc[i], si[i] * si[i]);
        const float cd = sAll - si[i];
        atomicAdd(&sacc[4 + i], cd * cd);
    }
    __syncthreads();

    if (t == 0) {
        double base = 0.0;
        for (int i = 0; i < 4; i++) {
            const double m = (double)cnt[i];
            if (cnt[i] > 0) {
                const double M = (double)n - m;
                const double pairs = m * (m - 1.0) * 0.5 + M * (M - 1.0) * 0.5;
                const double sumcos = ((double)sacc[i] - m) * 0.5 + ((double)sacc[4 + i] - M) * 0.5;
                base += (pairs - sumcos) / m;
            }
        }
        g_base = base;
        g_cntL = sL;
        g_cntN = sN;
        g_padL = (sL + 127) & ~127;
        g_padN = (sN + 127) & ~127;
    }
}

// ---------------- K4: gather rows into P (class L) and Q (non-L), zero-pad ----------------
__global__ void gather_kernel(int n) {
    const int b = blockIdx.x;
    const int side = (b >= n);          // 0 -> P, 1 -> Q
    const int r = side ? (b - n) : b;
    const int t = threadIdx.x;          // 64 threads, 8B each = 512B row
    const int cntX = side ? g_cntN : g_cntL;
    const int padX = side ? g_padN : g_padL;
    __nv_bfloat16* dst = side ? g_Q : g_P;
    if (r < cntX) {
        const int src = (side ? g_rowsN : g_rowsL)[r];
        ((uint2*)(dst + (size_t)r * E_DIM))[t] = ((const uint2*)(g_xb + (size_t)src * E_DIM))[t];
    } else if (r < padX) {
        ((uint2*)(dst + (size_t)r * E_DIM))[t] = make_uint2(0u, 0u);
    }
}

// ---------------- K5: relu-margin GEMM over P x Q^T ----------------
#define OFF_RED  0
#define OFF_A    1536
#define OFF_B    (OFF_A + NSTAGE * STAGE_BYTES)
#define SMEM_TOTAL (OFF_B + NSTAGE * STAGE_BYTES)

__global__ __launch_bounds__(256, 2) void relu_kernel() {
    const int bi = blockIdx.y;
    const int bj = blockIdx.x;
    if (bi * TILE >= g_padL || bj * TILE >= g_padN) return;

    extern __shared__ char smem[];
    const uint32_t sbase = smem_u32(smem);
    const int tid = threadIdx.x;
    const int wid = tid >> 5;
    const int lid = tid & 31;

    const uint4* __restrict__ srcA = (const uint4*)(g_P + (size_t)bi * TILE * E_DIM);
    const uint4* __restrict__ srcB = (const uint4*)(g_Q + (size_t)bj * TILE * E_DIM);

    auto load_chunk = [&](int c) {
        if (c < NCHUNK) {
            const int stage = c % NSTAGE;
            const uint32_t dA = sbase + OFF_A + stage * STAGE_BYTES;
            const uint32_t dB = sbase + OFF_B + stage * STAGE_BYTES;
            #pragma unroll
            for (int it = 0; it < 4; it++) {
                int v = tid + it * 256;
                int row = v >> 3;
                int q = v & 7;
                uint32_t d = (uint32_t)(row * SAW + q * 8) * 2u;
                int gsrc = row * 32 + c * 8 + q;
                cp_async16(dA + d, srcA + gsrc);
                cp_async16(dB + d, srcB + gsrc);
            }
        }
        cp_commit();
    };

    load_chunk(0);
    load_chunk(1);

    const int wm = wid & 1;
    const int wn = wid >> 1;
    const int rbase = wm * 64;
    const int cbase = wn * 32;

    float acc[4][4][4];
    #pragma unroll
    for (int mt = 0; mt < 4; mt++)
        #pragma unroll
        for (int nt = 0; nt < 4; nt++)
            #pragma unroll
            for (int q = 0; q < 4; q++) acc[mt][nt][q] = 0.f;

    const int mi = lid >> 3;
    const int mr = lid & 7;
    const uint32_t aOff = (uint32_t)((rbase + mr + (mi & 1) * 8) * SAW + (mi >> 1) * 8) * 2u;
    const uint32_t bOff = (uint32_t)((cbase + mr + (mi >> 1) * 8) * SAW + (mi & 1) * 8) * 2u;

    #pragma unroll
    for (int c = 0; c < NCHUNK; c++) {
        const int stage = c % NSTAGE;
        cp_wait1();
        __syncthreads();
        load_chunk(c + 2);

        const uint32_t aBase = sbase + OFF_A + stage * STAGE_BYTES + aOff;
        const uint32_t bBase = sbase + OFF_B + stage * STAGE_BYTES + bOff;

        #pragma unroll
        for (int k = 0; k < CHUNK; k += 16) {
            uint32_t af[4][4];
            uint32_t bf[4][2];
            #pragma unroll
            for (int mt = 0; mt < 4; mt++)
                ldsm_x4(af[mt], aBase + (uint32_t)(mt * 16 * SAW + k) * 2u);
            #pragma unroll
            for (int bt = 0; bt < 2; bt++) {
                uint32_t r[4];
                ldsm_x4(r, bBase + (uint32_t)(bt * 16 * SAW + k) * 2u);
                bf[2 * bt][0] = r[0]; bf[2 * bt][1] = r[1];
                bf[2 * bt + 1][0] = r[2]; bf[2 * bt + 1][1] = r[3];
            }
            #pragma unroll
            for (int mt = 0; mt < 4; mt++)
                #pragma unroll
                for (int nt = 0; nt < 4; nt++)
                    mma_16816(acc[mt][nt], af[mt], bf[nt]);
        }
    }

    // epilogue: relu(cos - 0.5); padded (zero) rows give relu(-0.5)=0 automatically
    float local = 0.f;
    #pragma unroll
    for (int mt = 0; mt < 4; mt++)
        #pragma unroll
        for (int nt = 0; nt < 4; nt++)
            #pragma unroll
            for (int q = 0; q < 4; q++)
                local += fmaxf(acc[mt][nt][q] - 0.5f, 0.0f);

    #pragma unroll
    for (int o = 16; o > 0; o >>= 1) local += __shfl_xor_sync(0xffffffffu, local, o);
    float* red = (float*)(smem + OFF_RED);
    if (lid == 0) red[wid] = local;
    __syncthreads();
    if (tid == 0) {
        float z = 0.f;
        #pragma unroll
        for (int i = 0; i < 8; i++) z += red[i];
        if (z != 0.f) atomicAdd(&g_sum, (double)z);
    }
}

// ---------------- K6: finalize ----------------
__global__ void finalize_kernel(float* out, double invN) {
    out[0] = (float)((g_base + g_sum) * invN);
}

extern "C" void kernel_launch(void* const* d_in, const int* in_sizes, int n_in,
                              void* d_out, int out_size) {
    const float* x = (const float*)d_in[0];
    const int* traw = (const int*)d_in[1];
    float* out = (float*)d_out;

    const int n = in_sizes[1];          // 8192
    const int gx = n / TILE;            // 64

    cudaFuncSetAttribute(relu_kernel, cudaFuncAttributeMaxDynamicSharedMemorySize, SMEM_TOTAL);

    prep_kernel<<<n, 256>>>(x, traw, n);
    classsum_kernel<<<n / 32, 256>>>(n);
    scalar_kernel<<<1, 256>>>(n);
    gather_kernel<<<2 * n, 64>>>(n);
    relu_kernel<<<dim3(gx, gx), 256, SMEM_TOTAL>>>();
    finalize_kernel<<<1, 1>>>(out, 1.0 / (double)n);
}